// round 14
// baseline (speedup 1.0000x reference)
#include <cuda_runtime.h>

// Problem constants
#define S      1048576        // 1024*1024
#define S4     (S / 4)        // float4 chunks per slab (262144)
#define TPB    256
#define NSLAB  10             // TT0:r0, TT1:r0..2, TT2:r0..2, TT3:r0..2
#define PBLK   128            // reduce blocks per slab
#define NITER  (S4 / (PBLK * TPB))   // 8 grid-stride iterations per thread
#define NCOMP  30             // 10 slabs x 3 q-components
#define RBLK   (NSLAB * PBLK) // 1280 reduce blocks
#define CBLK   1024           // bcast blocks: 1024*256 = S4 exactly (R3 shape)

// Deterministic scratch (no device allocation allowed)
__device__ float        g_bpart[NCOMP * PBLK];   // [comp][PBLK]
__device__ float        g_f[3];
__device__ unsigned int g_ctr = 0;               // reset by last block each call

// ---------------------------------------------------------------------------
// Kernel A: per-slab partial reduction (R12 body: __ldcs slab streams) with
// finalize fused into the LAST block (atomic-counter pattern).
//   slab = blockIdx.x % NSLAB   (same-s-range blocks co-scheduled -> z dedups)
// ---------------------------------------------------------------------------
__global__ void __launch_bounds__(TPB)
reduce_k(const float* __restrict__ z,
         const float* __restrict__ t0,
         const float* __restrict__ t1,
         const float* __restrict__ t2,
         const float* __restrict__ t3) {
    const int slab = blockIdx.x % NSLAB;
    const int blk  = blockIdx.x / NSLAB;

    const float* base;
    {
        const int r = (slab == 0) ? 0 : ((slab - 1) % 3);
        const float* t = (slab == 0) ? t0 : (slab <= 3 ? t1 : (slab <= 6 ? t2 : t3));
        base = t + (size_t)r * (3u * S);
    }
    const float4* bp = reinterpret_cast<const float4*>(base);
    const float4* zp = reinterpret_cast<const float4*>(z);

    float a0 = 0.0f, a1 = 0.0f, a2 = 0.0f;

    int c = blk * TPB + threadIdx.x;               // chunk index, stride PBLK*TPB
#pragma unroll
    for (int it = 0; it < NITER; it++, c += PBLK * TPB) {
        float4 zv = zp[c];                          // reused across 10 slabs -> cache
        const float4* p = bp + (size_t)c * 3;
        float4 v0 = __ldcs(p + 0);                  // streaming: zero reuse
        float4 v1 = __ldcs(p + 1);
        float4 v2 = __ldcs(p + 2);
        // 12 consecutive floats = 4 s x 3 q ; elem e -> (s=e/3, q=e%3)
        a0 += zv.x * v0.x;  a1 += zv.x * v0.y;  a2 += zv.x * v0.z;
        a0 += zv.y * v0.w;  a1 += zv.y * v1.x;  a2 += zv.y * v1.y;
        a0 += zv.z * v1.z;  a1 += zv.z * v1.w;  a2 += zv.z * v2.x;
        a0 += zv.w * v2.y;  a1 += zv.w * v2.z;  a2 += zv.w * v2.w;
    }

    // Warp reduction of 3 components
    const unsigned FULL = 0xffffffffu;
#pragma unroll
    for (int off = 16; off >= 1; off >>= 1) {
        a0 += __shfl_down_sync(FULL, a0, off);
        a1 += __shfl_down_sync(FULL, a1, off);
        a2 += __shfl_down_sync(FULL, a2, off);
    }

    __shared__ float sred[TPB / 32][3];
    const int warp = threadIdx.x >> 5;
    const int lane = threadIdx.x & 31;
    if (lane == 0) { sred[warp][0] = a0; sred[warp][1] = a1; sred[warp][2] = a2; }
    __syncthreads();

    if (threadIdx.x < 3) {
        float s = 0.0f;
#pragma unroll
        for (int w = 0; w < TPB / 32; w++) s += sred[w][threadIdx.x];
        g_bpart[(slab * 3 + threadIdx.x) * PBLK + blk] = s;   // deterministic
    }

    // ---- fused finalize: LAST block computes f = V0 @ V1 @ V2 @ V3 --------
    __shared__ bool amLast;
    __threadfence();
    if (threadIdx.x == 0)
        amLast = (atomicAdd(&g_ctr, 1u) == (unsigned)(RBLK - 1));
    __syncthreads();

    if (amLast) {
        __threadfence();                       // acquire: see all partials
        __shared__ float sV[32][8];
        const int comp = threadIdx.x >> 3;     // 0..31 (use 0..29)
        const int part = threadIdx.x & 7;      // 8 parts x 4 float4 = 128
        {
            float s = 0.0f;
            if (comp < NCOMP) {
                const float4* pp =
                    reinterpret_cast<const float4*>(g_bpart + comp * PBLK) + part * 4;
#pragma unroll
                for (int j = 0; j < 4; j++) { float4 v = pp[j]; s += v.x + v.y + v.z + v.w; }
            }
            sV[comp][part] = s;
        }
        __syncthreads();

        if (threadIdx.x == 0) {
            float V[NCOMP];
#pragma unroll
            for (int i = 0; i < NCOMP; i++) {
                float s = 0.0f;
#pragma unroll
                for (int j = 0; j < 8; j++) s += sV[i][j];
                V[i] = s;
            }
            float f0 = V[0], f1 = V[1], f2 = V[2];        // V0 : (1,3)
#pragma unroll
            for (int cc = 0; cc < 3; cc++) {              // V1,V2,V3 (3x3 [r*3+q])
                const float* M = V + 3 + cc * 9;
                float g0 = f0 * M[0] + f1 * M[3] + f2 * M[6];
                float g1 = f0 * M[1] + f1 * M[4] + f2 * M[7];
                float g2 = f0 * M[2] + f1 * M[5] + f2 * M[8];
                f0 = g0; f1 = g1; f2 = g2;
            }
            g_f[0] = f0; g_f[1] = f1; g_f[2] = f2;
            g_ctr = 0;                          // reset for next graph replay
        }
    }
}

// ---------------------------------------------------------------------------
// Kernel C: out[s] = f0*TT4[0,s,0] + f1*TT4[1,s,0] + f2*TT4[2,s,0]
// Lean R3 shape (its 6.4us best): 1024 blocks, 3 loads + 1 store per thread.
// ---------------------------------------------------------------------------
__global__ void __launch_bounds__(TPB)
bcast_k(const float* __restrict__ t4, float* __restrict__ out) {
    const int idx = blockIdx.x * TPB + threadIdx.x;   // 0 .. S4-1 exact

    const float4* p = reinterpret_cast<const float4*>(t4);
    float4 av = __ldcs(p + idx);
    float4 bv = __ldcs(p + S4 + idx);
    float4 cv = __ldcs(p + 2 * S4 + idx);

    const float f0 = g_f[0];           // 3 broadcast loads (L2-resident)
    const float f1 = g_f[1];
    const float f2 = g_f[2];

    float4 o;
    o.x = f0 * av.x + f1 * bv.x + f2 * cv.x;
    o.y = f0 * av.y + f1 * bv.y + f2 * cv.y;
    o.z = f0 * av.z + f1 * bv.z + f2 * cv.z;
    o.w = f0 * av.w + f1 * bv.w + f2 * cv.w;
    __stcs(reinterpret_cast<float4*>(out) + idx, o);
}

// ---------------------------------------------------------------------------
extern "C" void kernel_launch(void* const* d_in, const int* in_sizes, int n_in,
                              void* d_out, int out_size) {
    const float* z  = (const float*)d_in[0];
    const float* t0 = (const float*)d_in[1];
    const float* t1 = (const float*)d_in[2];
    const float* t2 = (const float*)d_in[3];
    const float* t3 = (const float*)d_in[4];
    const float* t4 = (const float*)d_in[5];
    float* out = (float*)d_out;

    reduce_k<<<RBLK, TPB>>>(z, t0, t1, t2, t3);
    bcast_k<<<CBLK, TPB>>>(t4, out);
}

// round 16
// speedup vs baseline: 1.1969x; 1.1969x over previous
#include <cuda_runtime.h>

// Problem constants
#define S      1048576        // 1024*1024
#define S4     (S / 4)        // float4 chunks per slab (262144)
#define TPB    256
#define NSLAB  10             // TT0:r0, TT1:r0..2, TT2:r0..2, TT3:r0..2
#define PBLK   128            // reduce blocks per slab
#define NITER  (S4 / (PBLK * TPB))   // 8 grid-stride iterations per thread
#define NCOMP  30             // 10 slabs x 3 q-components
#define RBLK   (NSLAB * PBLK) // 1280 reduce blocks
#define CBLK   1024           // bcast blocks: 1024*256 = S4 exactly

// Deterministic scratch (no device allocation allowed)
__device__ float g_bpart[NCOMP * PBLK];   // [comp][PBLK]
__device__ float g_f[3];

// ---------------------------------------------------------------------------
// Kernel A: per-slab partial reduction. R12 body verbatim: __ldcs on slab
// streams (zero reuse -> evict-first keeps z cached), NO fence, NO atomics.
//   slab = blockIdx.x % NSLAB  (same-s-range blocks co-scheduled -> z dedups)
// ---------------------------------------------------------------------------
__global__ void __launch_bounds__(TPB)
reduce_k(const float* __restrict__ z,
         const float* __restrict__ t0,
         const float* __restrict__ t1,
         const float* __restrict__ t2,
         const float* __restrict__ t3) {
    const int slab = blockIdx.x % NSLAB;
    const int blk  = blockIdx.x / NSLAB;

    const float* base;
    {
        const int r = (slab == 0) ? 0 : ((slab - 1) % 3);
        const float* t = (slab == 0) ? t0 : (slab <= 3 ? t1 : (slab <= 6 ? t2 : t3));
        base = t + (size_t)r * (3u * S);
    }
    const float4* bp = reinterpret_cast<const float4*>(base);
    const float4* zp = reinterpret_cast<const float4*>(z);

    float a0 = 0.0f, a1 = 0.0f, a2 = 0.0f;

    int c = blk * TPB + threadIdx.x;               // chunk index, stride PBLK*TPB
#pragma unroll
    for (int it = 0; it < NITER; it++, c += PBLK * TPB) {
        float4 zv = zp[c];                          // reused across 10 slabs -> cache
        const float4* p = bp + (size_t)c * 3;
        float4 v0 = __ldcs(p + 0);                  // streaming: zero reuse
        float4 v1 = __ldcs(p + 1);
        float4 v2 = __ldcs(p + 2);
        // 12 consecutive floats = 4 s x 3 q ; elem e -> (s=e/3, q=e%3)
        a0 += zv.x * v0.x;  a1 += zv.x * v0.y;  a2 += zv.x * v0.z;
        a0 += zv.y * v0.w;  a1 += zv.y * v1.x;  a2 += zv.y * v1.y;
        a0 += zv.z * v1.z;  a1 += zv.z * v1.w;  a2 += zv.z * v2.x;
        a0 += zv.w * v2.y;  a1 += zv.w * v2.z;  a2 += zv.w * v2.w;
    }

    // Warp reduction of 3 components
    const unsigned FULL = 0xffffffffu;
#pragma unroll
    for (int off = 16; off >= 1; off >>= 1) {
        a0 += __shfl_down_sync(FULL, a0, off);
        a1 += __shfl_down_sync(FULL, a1, off);
        a2 += __shfl_down_sync(FULL, a2, off);
    }

    __shared__ float sred[TPB / 32][3];
    const int warp = threadIdx.x >> 5;
    const int lane = threadIdx.x & 31;
    if (lane == 0) { sred[warp][0] = a0; sred[warp][1] = a1; sred[warp][2] = a2; }
    __syncthreads();

    if (threadIdx.x < 3) {
        float s = 0.0f;
#pragma unroll
        for (int w = 0; w < TPB / 32; w++) s += sred[w][threadIdx.x];
        g_bpart[(slab * 3 + threadIdx.x) * PBLK + blk] = s;   // deterministic
    }
}

// ---------------------------------------------------------------------------
// Kernel B: tiny finalize, one block. Coalesced float4 reads of g_bpart
// (L2-resident), then f = V0 @ V1 @ V2 @ V3 on thread 0.
// ---------------------------------------------------------------------------
__global__ void __launch_bounds__(TPB)
finalize_k() {
    __shared__ float sV[32][8];
    const int comp = threadIdx.x >> 3;     // 0..31 (use 0..29)
    const int part = threadIdx.x & 7;      // 8 parts x 4 float4 = 128 partials
    {
        float s = 0.0f;
        if (comp < NCOMP) {
            const float4* pp =
                reinterpret_cast<const float4*>(g_bpart + comp * PBLK) + part * 4;
#pragma unroll
            for (int j = 0; j < 4; j++) { float4 v = pp[j]; s += v.x + v.y + v.z + v.w; }
        }
        sV[comp][part] = s;
    }
    __syncthreads();

    if (threadIdx.x == 0) {
        float V[NCOMP];
#pragma unroll
        for (int i = 0; i < NCOMP; i++) {
            float s = 0.0f;
#pragma unroll
            for (int j = 0; j < 8; j++) s += sV[i][j];
            V[i] = s;
        }
        float f0 = V[0], f1 = V[1], f2 = V[2];        // V0 : (1,3)
#pragma unroll
        for (int cc = 0; cc < 3; cc++) {              // V1,V2,V3 (3x3 [r*3+q])
            const float* M = V + 3 + cc * 9;
            float g0 = f0 * M[0] + f1 * M[3] + f2 * M[6];
            float g1 = f0 * M[1] + f1 * M[4] + f2 * M[7];
            float g2 = f0 * M[2] + f1 * M[5] + f2 * M[8];
            f0 = g0; f1 = g1; f2 = g2;
        }
        g_f[0] = f0; g_f[1] = f1; g_f[2] = f2;
    }
}

// ---------------------------------------------------------------------------
// Kernel C: out[s] = f0*TT4[0,s,0] + f1*TT4[1,s,0] + f2*TT4[2,s,0]
// Exact R3 shape (6.4us best): plain loads/stores, 1024 blocks.
// ---------------------------------------------------------------------------
__global__ void __launch_bounds__(TPB)
bcast_k(const float* __restrict__ t4, float* __restrict__ out) {
    const int idx = blockIdx.x * TPB + threadIdx.x;   // 0 .. S4-1 exact
    const float f0 = g_f[0];
    const float f1 = g_f[1];
    const float f2 = g_f[2];

    const float4* p = reinterpret_cast<const float4*>(t4);
    float4 a = p[idx];
    float4 b = p[S4 + idx];
    float4 c = p[2 * S4 + idx];

    float4 o;
    o.x = f0 * a.x + f1 * b.x + f2 * c.x;
    o.y = f0 * a.y + f1 * b.y + f2 * c.y;
    o.z = f0 * a.z + f1 * b.z + f2 * c.z;
    o.w = f0 * a.w + f1 * b.w + f2 * c.w;
    reinterpret_cast<float4*>(out)[idx] = o;
}

// ---------------------------------------------------------------------------
extern "C" void kernel_launch(void* const* d_in, const int* in_sizes, int n_in,
                              void* d_out, int out_size) {
    const float* z  = (const float*)d_in[0];
    const float* t0 = (const float*)d_in[1];
    const float* t1 = (const float*)d_in[2];
    const float* t2 = (const float*)d_in[3];
    const float* t3 = (const float*)d_in[4];
    const float* t4 = (const float*)d_in[5];
    float* out = (float*)d_out;

    reduce_k<<<RBLK, TPB>>>(z, t0, t1, t2, t3);
    finalize_k<<<1, TPB>>>();
    bcast_k<<<CBLK, TPB>>>(t4, out);
}